// round 17
// baseline (speedup 1.0000x reference)
#include <cuda_runtime.h>
#include <math.h>

#define NG   8
#define ND   16
#define NL   1024
#define NB   16
#define NE   8
#define NOUT 64
#define NKS  3
#define NK   4
#define NLP  1022
#define TILE 128
#define NTILES 8
#define XPAD 136           // xs row stride: 136%32=8 -> conflict-free B-frags
#define HTP  68            // transposed h-strip col stride (68%32=4)

typedef unsigned int u32;

// Scratch (static device globals — no allocation)
__device__ float g_gates[NG*NB*NE];
__device__ float g_beff[NG*NB*NOUT];
// W_eff in mma-fragment order: [blk][mt(4)][kt(8)][lane(32)] x float4
__device__ float g_wfrag[NG*NB*4*8*32*4];
// conv1 weights in mma-fragment order: [g][mt(4)][ks(3)][kt(2)][lane(32)] x float4
__device__ float g_w1frag[NG*4*3*2*32*4];

__device__ __forceinline__ float tanh_fast(float x) {
    float r;
    asm("tanh.approx.f32 %0, %1;" : "=f"(r) : "f"(x));
    return r;
}
__device__ __forceinline__ float round_tf32(float x) {
    u32 r;
    asm("cvt.rna.tf32.f32 %0, %1;" : "=r"(r) : "f"(x));
    return __uint_as_float(r);
}
__device__ __forceinline__ void mma_tf32(float& c0, float& c1, float& c2, float& c3,
                                         u32 a0, u32 a1, u32 a2, u32 a3,
                                         u32 b0, u32 b1) {
    asm("mma.sync.aligned.m16n8k8.row.col.f32.tf32.tf32.f32 "
        "{%0,%1,%2,%3}, {%4,%5,%6,%7}, {%8,%9}, {%0,%1,%2,%3};"
        : "+f"(c0), "+f"(c1), "+f"(c2), "+f"(c3)
        : "r"(a0), "r"(a1), "r"(a2), "r"(a3), "r"(b0), "r"(b1));
}

__device__ __forceinline__ float cv_sq(const float* v) {
    float m = 0.f;
    #pragma unroll
    for (int i = 0; i < NE; i++) m += v[i];
    m *= (1.f / NE);
    float var = 0.f;
    #pragma unroll
    for (int i = 0; i < NE; i++) { float d = v[i] - m; var += d * d; }
    var *= (1.f / (NE - 1));
    return var / (m * m + 1e-10f);
}

// ---------------------------------------------------------------------------
// Kernel A: gates + W_eff fold -> fragment layout, 4x parallel over mt.
// (unchanged from R16: measured ~2.7us)
// ---------------------------------------------------------------------------
__global__ __launch_bounds__(256)
void prep_kernel(const float* __restrict__ x,
                 const float* __restrict__ w_gate,
                 const float* __restrict__ w1,
                 const float* __restrict__ w2,
                 const float* __restrict__ b2,
                 float* __restrict__ out) {
    const int mt = blockIdx.x;    // 0..3
    const int b  = blockIdx.y;
    const int g  = blockIdx.z;
    const int blk = g * NB + b;
    const int t = threadIdx.x;
    const int c = t & 31;
    const int r = t >> 5;

    __shared__ float gsm[NE];
    __shared__ float wef_s[16 * 65];

    if (r == 0) {
        const float* xb0 = x + (size_t)b * (NG * ND * NL) + (size_t)g * ND * NL;
        float plog[NE];
        #pragma unroll
        for (int e = 0; e < NE; e++) plog[e] = 0.f;
        #pragma unroll
        for (int i = c; i < ND * 5; i += 32) {
            int d = i / 5, j = i % 5;
            float xv = xb0[(size_t)d * NL + (NL - 6 + j)];
            const float4* w4 = (const float4*)(w_gate + ((size_t)g * ND * 5 + i) * NE);
            float4 wa = w4[0], wb = w4[1];
            plog[0] += xv * wa.x; plog[1] += xv * wa.y;
            plog[2] += xv * wa.z; plog[3] += xv * wa.w;
            plog[4] += xv * wb.x; plog[5] += xv * wb.y;
            plog[6] += xv * wb.z; plog[7] += xv * wb.w;
        }
        #pragma unroll
        for (int off = 16; off >= 1; off >>= 1)
            #pragma unroll
            for (int e = 0; e < NE; e++)
                plog[e] += __shfl_xor_sync(0xffffffffu, plog[e], off);

        float m = plog[0];
        #pragma unroll
        for (int e = 1; e < NE; e++) m = fmaxf(m, plog[e]);
        float p[NE]; float s = 0.f;
        #pragma unroll
        for (int e = 0; e < NE; e++) { p[e] = __expf(plog[e] - m); s += p[e]; }
        float inv = 1.f / s;
        #pragma unroll
        for (int e = 0; e < NE; e++) p[e] *= inv;

        int rank[NE];
        #pragma unroll
        for (int e = 0; e < NE; e++) {
            int rk = 0;
            #pragma unroll
            for (int j = 0; j < NE; j++)
                rk += (p[j] > p[e]) || (p[j] == p[e] && j < e);
            rank[e] = rk;
        }
        float s4 = 0.f;
        #pragma unroll
        for (int e = 0; e < NE; e++) s4 += (rank[e] < NK) ? p[e] : 0.f;
        const float invs4 = 1.f / (s4 + 1e-6f);

        if (c < NE) {
            const float gv = (rank[c] < NK) ? p[c] * invs4 : 0.f;
            gsm[c] = gv;
            if (mt == 0) {
                const size_t combine_sz = (size_t)NB * NG * NOUT * NLP;
                g_gates[blk * NE + c] = gv;
                out[combine_sz + 1 + (size_t)(b * NE + c) * NG + g] = gv;
            }
        }
    }

    if (b == 0 && t < 192) {
        const float* w1g = w1 + (size_t)g * NOUT * (ND * NKS);
        const int lane = t & 31;
        const int kt   = (t >> 5) & 1;
        const int ks   = t >> 6;
        const int fgid = lane >> 2, ftg = lane & 3;
        const int row0 = mt * 16 + fgid;
        const int colA = (kt * 8 + ftg) * NKS + ks;
        const int colB = (kt * 8 + ftg + 4) * NKS + ks;
        float4 v;
        v.x = round_tf32(w1g[row0 * (ND * NKS) + colA]);
        v.y = round_tf32(w1g[(row0 + 8) * (ND * NKS) + colA]);
        v.z = round_tf32(w1g[row0 * (ND * NKS) + colB]);
        v.w = round_tf32(w1g[(row0 + 8) * (ND * NKS) + colB]);
        ((float4*)g_w1frag)[(size_t)g * 768 + mt * 192 + ks * 64 + kt * 32 + lane] = v;
    }
    __syncthreads();

    {
        float gv[NE];
        #pragma unroll
        for (int e = 0; e < NE; e++) gv[e] = gsm[e];
        const float* w2g = w2 + (size_t)g * NOUT * NE * NOUT;
        #pragma unroll
        for (int it = 0; it < 4; it++) {
            int idx = t + it * 256;
            int op = idx >> 6, k = idx & 63;
            const float* wrow = w2g + (size_t)(mt * 16 + op) * NE * NOUT + k;
            float acc = 0.f;
            #pragma unroll
            for (int e = 0; e < NE; e++) acc += gv[e] * wrow[e * NOUT];
            wef_s[op * 65 + k] = round_tf32(acc);
        }
        if (mt == 0 && t < NOUT) {
            const float* brow = b2 + (size_t)g * NOUT * NE + t * NE;
            float acc = 0.f;
            #pragma unroll
            for (int e = 0; e < NE; e++) acc += gv[e] * brow[e];
            g_beff[blk * NOUT + t] = acc;
        }
    }
    __syncthreads();

    {
        const int lane = t & 31, kt = t >> 5;
        const int fgid = lane >> 2, ftg = lane & 3;
        const int k0 = kt * 8;
        float4 v;
        v.x = wef_s[fgid * 65 + k0 + ftg];
        v.y = wef_s[(fgid + 8) * 65 + k0 + ftg];
        v.z = wef_s[fgid * 65 + k0 + ftg + 4];
        v.w = wef_s[(fgid + 8) * 65 + k0 + ftg + 4];
        ((float4*)g_wfrag)[(size_t)blk * 1024 + mt * 256 + t] = v;
    }
}

// ---------------------------------------------------------------------------
// Main kernel: column-strip ownership. Warp w owns out cols [16w,16w+16) of
// its block's 2 tiles, for ALL 64 rows. Phase2->phase3 is warp-local (no
// block barrier). grid (4, NB, NG) = 512 blocks, 256 threads.
// ---------------------------------------------------------------------------
__global__ __launch_bounds__(256, 4)
void main_kernel(const float* __restrict__ x,
                 const float* __restrict__ b1,
                 float* __restrict__ out) {
    const int bx  = blockIdx.x;
    const int b   = blockIdx.y;
    const int g   = blockIdx.z;
    const int blk = g * NB + b;

    __shared__ float xs[2][ND * XPAD];    // both tiles, read-only after stage
    __shared__ float hT[8][16 * HTP];     // per-warp transposed h strip
    __shared__ float b1s[NOUT];
    __shared__ float bes[NOUT];

    const int t = threadIdx.x;
    const int c = t & 31;
    const int r = t >> 5;                 // warp = column strip
    const int gid = c >> 2;
    const int tg  = c & 3;

    const float* xb0 = x + (size_t)b * (NG * ND * NL) + (size_t)g * ND * NL;

    // ---- stage both x tiles + biases; single block barrier ----
    for (int idx = t; idx < 2 * ND * XPAD; idx += 256) {
        const int buf = idx / (ND * XPAD);
        const int rem = idx - buf * (ND * XPAD);
        const int d = rem / XPAD, l = rem - d * XPAD;
        const int gx = (bx * 2 + buf) * TILE + l;
        xs[buf][rem] = round_tf32((gx < NL) ? xb0[(size_t)d * NL + gx] : 0.f);
    }
    if (t < NOUT) {
        b1s[t] = b1[g * NOUT + t];
        bes[t] = g_beff[blk * NOUT + t];
    }
    __syncthreads();

    const float4* wf1g = (const float4*)g_w1frag + (size_t)g * 768;
    const float4* wfrg = (const float4*)g_wfrag + (size_t)blk * 1024;
    float* myh = hT[r];

    #pragma unroll
    for (int it = 0; it < 2; it++) {
        const int l0g  = (bx * 2 + it) * TILE;
        const int tlen = min(TILE, NLP - l0g);
        const u32* xsu = (const u32*)xs[it];
        const int cbase = r * 16;          // strip base within tile

        // ---- phase 2: h strip (64 rows x 16 cols) via tf32 mma ----
        #pragma unroll
        for (int mtl = 0; mtl < 4; mtl++) {
            const float bv0 = b1s[mtl * 16 + gid];
            const float bv1 = b1s[mtl * 16 + gid + 8];
            // 6 A-fragments for this row block (L1-resident)
            u32 a[6][4];
            #pragma unroll
            for (int ks = 0; ks < NKS; ks++)
                #pragma unroll
                for (int kt = 0; kt < 2; kt++) {
                    const float4 af = wf1g[mtl * 192 + ks * 64 + kt * 32 + c];
                    a[ks * 2 + kt][0] = __float_as_uint(af.x);
                    a[ks * 2 + kt][1] = __float_as_uint(af.y);
                    a[ks * 2 + kt][2] = __float_as_uint(af.z);
                    a[ks * 2 + kt][3] = __float_as_uint(af.w);
                }
            #pragma unroll
            for (int ntl = 0; ntl < 2; ntl++) {
                float c0 = bv0, c1 = bv0, c2 = bv1, c3 = bv1;
                #pragma unroll
                for (int ks = 0; ks < NKS; ks++)
                    #pragma unroll
                    for (int kt = 0; kt < 2; kt++) {
                        const int d0 = kt * 8;
                        const int ncol = cbase + ntl * 8 + gid + ks;
                        const u32 b0 = xsu[(d0 + tg) * XPAD + ncol];
                        const u32 b1v = xsu[(d0 + tg + 4) * XPAD + ncol];
                        mma_tf32(c0, c1, c2, c3,
                                 a[ks * 2 + kt][0], a[ks * 2 + kt][1],
                                 a[ks * 2 + kt][2], a[ks * 2 + kt][3], b0, b1v);
                    }
                // store transposed: myh[col*HTP + row]
                const int cs = ntl * 8 + tg * 2;
                const int row0 = mtl * 16 + gid;
                myh[cs * HTP + row0]           = round_tf32(tanh_fast(c0));
                myh[(cs + 1) * HTP + row0]     = round_tf32(tanh_fast(c1));
                myh[cs * HTP + row0 + 8]       = round_tf32(tanh_fast(c2));
                myh[(cs + 1) * HTP + row0 + 8] = round_tf32(tanh_fast(c3));
            }
        }
        __syncwarp();

        // ---- phase 3: out strip = W_eff @ h + b_eff (warp-local h) ----
        #pragma unroll
        for (int mtl = 0; mtl < 4; mtl++) {
            const float bv0 = bes[mtl * 16 + gid];
            const float bv1 = bes[mtl * 16 + gid + 8];
            float cacc[2][4];
            #pragma unroll
            for (int ntl = 0; ntl < 2; ntl++) {
                cacc[ntl][0] = bv0; cacc[ntl][1] = bv0;
                cacc[ntl][2] = bv1; cacc[ntl][3] = bv1;
            }
            #pragma unroll
            for (int kt = 0; kt < 8; kt++) {
                const float4 af = wfrg[mtl * 256 + kt * 32 + c];
                const int k0 = kt * 8;
                const u32 a0 = __float_as_uint(af.x);
                const u32 a1 = __float_as_uint(af.y);
                const u32 a2 = __float_as_uint(af.z);
                const u32 a3 = __float_as_uint(af.w);
                #pragma unroll
                for (int ntl = 0; ntl < 2; ntl++) {
                    const int cs = ntl * 8 + gid;
                    const u32 b0 = __float_as_uint(myh[cs * HTP + k0 + tg]);
                    const u32 b1v = __float_as_uint(myh[cs * HTP + k0 + tg + 4]);
                    mma_tf32(cacc[ntl][0], cacc[ntl][1], cacc[ntl][2], cacc[ntl][3],
                             a0, a1, a2, a3, b0, b1v);
                }
            }
            const int row0 = mtl * 16 + gid;
            #pragma unroll
            for (int ntl = 0; ntl < 2; ntl++) {
                const int colt = cbase + ntl * 8 + tg * 2;
                float* row0p = out + ((size_t)(b * NG + g) * NOUT + row0) * NLP + l0g + colt;
                float* row1p = row0p + 8 * NLP;
                if (colt + 1 < tlen) {
                    *(float2*)row0p = make_float2(cacc[ntl][0], cacc[ntl][1]);
                    *(float2*)row1p = make_float2(cacc[ntl][2], cacc[ntl][3]);
                } else if (colt < tlen) {
                    row0p[0] = cacc[ntl][0];
                    row1p[0] = cacc[ntl][2];
                }
            }
        }
        __syncwarp();
    }

    // ---- loss tail: block (0,0,0) only ----
    if (bx == 0 && b == 0 && g == 0) {
        __syncthreads();                 // all warps done with xs before reuse
        float* s_imp = (float*)xs;
        float* s_ld  = (float*)xs + NG * NE;
        float* lsum  = (float*)xs + 2 * NG * NE;
        if (t < NG * NE) {
            const int gg = t >> 3, e = t & 7;
            float imp = 0.f, ld = 0.f;
            #pragma unroll
            for (int bb = 0; bb < NB; bb++) {
                float v = g_gates[((gg * NB + bb) * NE) + e];
                imp += v;
                ld  += (v > 0.f) ? 1.f : 0.f;
            }
            s_imp[gg * NE + e] = imp;
            s_ld[gg * NE + e]  = ld;
        }
        __syncthreads();
        if (t < NG) lsum[t] = cv_sq(&s_imp[t * NE]) + cv_sq(&s_ld[t * NE]);
        __syncthreads();
        if (t == 0) {
            float total = 0.f;
            #pragma unroll
            for (int i = 0; i < NG; i++) total += lsum[i];
            out[(size_t)NB * NG * NOUT * NLP] = 0.01f * total;
        }
    }
}

// ---------------------------------------------------------------------------
extern "C" void kernel_launch(void* const* d_in, const int* in_sizes, int n_in,
                              void* d_out, int out_size) {
    const float* x       = (const float*)d_in[0];
    const float* w_gate  = (const float*)d_in[1];
    const float* conv1_w = (const float*)d_in[2];
    const float* conv1_b = (const float*)d_in[3];
    const float* conv2_w = (const float*)d_in[4];
    const float* conv2_b = (const float*)d_in[5];
    float* out = (float*)d_out;

    prep_kernel<<<dim3(4, NB, NG), 256>>>(x, w_gate, conv1_w, conv2_w, conv2_b, out);
    main_kernel<<<dim3(NTILES / 2, NB, NG), 256>>>(x, conv1_b, out);
}